// round 7
// baseline (speedup 1.0000x reference)
#include <cuda_runtime.h>
#include <math.h>

#define NNODES 100000
#define NEDGES 3200000
#define HD 64
#define DINP 15
#define DOUT 12
#define NTYPE 5
#define NGRAPH 256
#define NSTEPS 6

#define SCAN_B 1024
#define NB ((NNODES + SCAN_B - 1) / SCAN_B)   // 98

// ---------------- scratch (device globals; no allocation) ----------------
__device__ float g_out0[NNODES * HD];
__device__ float g_h[NNODES * HD];
__device__ float g_m[NNODES * HD];
__device__ float g_i1[NNODES * HD];
__device__ float g_j1[NNODES * HD];
__device__ float g_scratch[(size_t)NNODES * 384];   // agg[N,320] / gx[N,192] / gh[N,192]
__device__ float g_deginv[NNODES];
__device__ int   g_rowptr[NNODES + 1];
__device__ int   g_cnt[NNODES];
__device__ int   g_cursor[NNODES];
__device__ int   g_bsums[128];
__device__ int   g_ecsr[NEDGES];

// ---------------- CSR build ----------------
__global__ void zero_cnt_kernel() {
    int i = blockIdx.x * blockDim.x + threadIdx.x;
    if (i < NNODES) g_cnt[i] = 0;
}

__global__ void hist_kernel(const int* __restrict__ dst) {
    int e = blockIdx.x * blockDim.x + threadIdx.x;
    if (e < NEDGES) atomicAdd(&g_cnt[dst[e]], 1);
}

__global__ void scan1_kernel() {
    __shared__ int s[SCAN_B];
    int tid = threadIdx.x;
    int g = blockIdx.x * SCAN_B + tid;
    int v = (g < NNODES) ? g_cnt[g] : 0;
    s[tid] = v;
    __syncthreads();
    for (int off = 1; off < SCAN_B; off <<= 1) {
        int t = (tid >= off) ? s[tid - off] : 0;
        __syncthreads();
        s[tid] += t;
        __syncthreads();
    }
    if (g < NNODES) g_rowptr[g] = s[tid] - v;          // block-local exclusive
    if (tid == SCAN_B - 1) g_bsums[blockIdx.x] = s[tid];
}

__global__ void scan2_kernel() {
    __shared__ int s[128];
    int tid = threadIdx.x;
    int v = (tid < NB) ? g_bsums[tid] : 0;
    s[tid] = v;
    __syncthreads();
    for (int off = 1; off < 128; off <<= 1) {
        int t = (tid >= off) ? s[tid - off] : 0;
        __syncthreads();
        s[tid] += t;
        __syncthreads();
    }
    if (tid < NB) g_bsums[tid] = s[tid] - v;           // exclusive block offsets
    if (tid == 127) g_rowptr[NNODES] = s[127];         // = E
}

__global__ void scan3_kernel() {
    int g = blockIdx.x * blockDim.x + threadIdx.x;
    if (g >= NNODES) return;
    g_rowptr[g] += g_bsums[g >> 10];
    g_cursor[g] = 0;
    int d = g_cnt[g];
    g_deginv[g] = 1.0f / (float)(d > 0 ? d : 1);
}

__global__ void scatter_kernel(const int* __restrict__ src,
                               const int* __restrict__ dst,
                               const int* __restrict__ typ) {
    int e = blockIdx.x * blockDim.x + threadIdx.x;
    if (e >= NEDGES) return;
    int d = dst[e];
    int pos = atomicAdd(&g_cursor[d], 1);
    g_ecsr[g_rowptr[d] + pos] = src[e] | (typ[e] << 17);  // N < 2^17, type < 8
}

// ---------------- generic fp32 GEMM: C[nrows,M] = A[nrows,K] @ B[K,M] + epilogue ----
// EPI: 0 = +bias; 1 = relu(+bias); 2 = relu(acc*rowscale + bias); 3 = sigmoid(+bias)
template <int EPI, bool CONCAT>
__global__ void __launch_bounds__(256)
gemm_kernel(const float* __restrict__ A, const float* __restrict__ A2,
            const float* __restrict__ B, const float* __restrict__ bias,
            const float* __restrict__ rowscale, float* __restrict__ C,
            int nrows, int K, int M) {
    __shared__ float As[128 * 17];     // [m][k], stride 17 (conflict padding)
    __shared__ float Bs[16 * 64];      // [k][n]
    const int tid = threadIdx.x;
    const int tx = tid & 15;           // col group -> cols tx*4 .. tx*4+3
    const int ty = tid >> 4;           // row group -> rows ty*8 .. ty*8+7
    const int rowBlk = blockIdx.x * 128;
    const int colBlk = blockIdx.y * 64;

    float acc[8][4];
#pragma unroll
    for (int i = 0; i < 8; i++)
#pragma unroll
        for (int j = 0; j < 4; j++) acc[i][j] = 0.f;

    const int m_ld = tid >> 1;
    const int kh = (tid & 1) * 8;
    const int grow = rowBlk + m_ld;

    for (int k0 = 0; k0 < K; k0 += 16) {
        // A tile: 128 x 16
#pragma unroll
        for (int j = 0; j < 8; j++) {
            int kk = k0 + kh + j;
            float v = 0.f;
            if (grow < nrows && kk < K) {
                if (CONCAT) v = (kk < HD) ? A[grow * HD + kk] : A2[grow * HD + (kk - HD)];
                else        v = A[(size_t)grow * K + kk];
            }
            As[m_ld * 17 + kh + j] = v;
        }
        // B tile: 16 x 64
        {
            int idx = tid * 4;
            int bk = idx >> 6;
            int bn = idx & 63;
#pragma unroll
            for (int j = 0; j < 4; j++) {
                int gk = k0 + bk, gn = colBlk + bn + j;
                Bs[bk * 64 + bn + j] = (gk < K && gn < M) ? __ldg(&B[gk * M + gn]) : 0.f;
            }
        }
        __syncthreads();
#pragma unroll
        for (int kk = 0; kk < 16; kk++) {
            float4 b4 = *reinterpret_cast<const float4*>(&Bs[kk * 64 + tx * 4]);
            float a[8];
#pragma unroll
            for (int i = 0; i < 8; i++) a[i] = As[(ty * 8 + i) * 17 + kk];
#pragma unroll
            for (int i = 0; i < 8; i++) {
                acc[i][0] += a[i] * b4.x;
                acc[i][1] += a[i] * b4.y;
                acc[i][2] += a[i] * b4.z;
                acc[i][3] += a[i] * b4.w;
            }
        }
        __syncthreads();
    }
#pragma unroll
    for (int i = 0; i < 8; i++) {
        int r = rowBlk + ty * 8 + i;
        if (r >= nrows) break;
        float rs = (EPI == 2) ? rowscale[r] : 1.f;
#pragma unroll
        for (int j = 0; j < 4; j++) {
            int c = colBlk + tx * 4 + j;
            if (c >= M) continue;
            float v = acc[i][j];
            if (EPI == 2) v *= rs;
            v += bias[c];
            if (EPI == 1 || EPI == 2) v = fmaxf(v, 0.f);
            if (EPI == 3) v = 1.f / (1.f + expf(-v));
            C[(size_t)r * M + c] = v;
        }
    }
}

// ---------------- per-type neighbor aggregation (warp per node) ----------------
// agg[n, t*64 + c] = sum over in-edges of type t of out[src, c]
__global__ void agg_kernel(const float2* __restrict__ out2, float2* __restrict__ agg2) {
    int w = (blockIdx.x * blockDim.x + threadIdx.x) >> 5;
    int lane = threadIdx.x & 31;
    if (w >= NNODES) return;
    int s = g_rowptr[w];
    int e = g_rowptr[w + 1];
    float2 acc[NTYPE];
#pragma unroll
    for (int t = 0; t < NTYPE; t++) { acc[t].x = 0.f; acc[t].y = 0.f; }
    int i = s;
    for (; i + 1 < e; i += 2) {
        int e0 = __ldg(&g_ecsr[i]);
        int e1 = __ldg(&g_ecsr[i + 1]);
        float2 v0 = out2[(e0 & 0x1FFFF) * 32 + lane];
        float2 v1 = out2[(e1 & 0x1FFFF) * 32 + lane];
        int t0 = e0 >> 17, t1 = e1 >> 17;
#pragma unroll
        for (int t = 0; t < NTYPE; t++) {
            if (t0 == t) { acc[t].x += v0.x; acc[t].y += v0.y; }
            if (t1 == t) { acc[t].x += v1.x; acc[t].y += v1.y; }
        }
    }
    if (i < e) {
        int e0 = __ldg(&g_ecsr[i]);
        float2 v0 = out2[(e0 & 0x1FFFF) * 32 + lane];
        int t0 = e0 >> 17;
#pragma unroll
        for (int t = 0; t < NTYPE; t++)
            if (t0 == t) { acc[t].x += v0.x; acc[t].y += v0.y; }
    }
    size_t base = (size_t)w * (NTYPE * 32);
#pragma unroll
    for (int t = 0; t < NTYPE; t++) agg2[base + t * 32 + lane] = acc[t];
}

// ---------------- GRU elementwise ----------------
__global__ void gru_kernel(const float* __restrict__ gx, const float* __restrict__ gh,
                           float* __restrict__ h) {
    int idx = blockIdx.x * blockDim.x + threadIdx.x;
    if (idx >= NNODES * HD) return;
    int n = idx >> 6, c = idx & 63;
    size_t b = (size_t)n * 192 + c;
    float xr = gx[b], xz = gx[b + 64], xn = gx[b + 128];
    float hr = gh[b], hz = gh[b + 64], hn = gh[b + 128];
    float r = 1.f / (1.f + expf(-(xr + hr)));
    float z = 1.f / (1.f + expf(-(xz + hz)));
    float nn = tanhf(xn + r * hn);
    float hv = h[idx];
    h[idx] = (1.f - z) * nn + z * hv;
}

__global__ void copy4_kernel(const float4* __restrict__ a, float4* __restrict__ b, int n4) {
    int i = blockIdx.x * blockDim.x + threadIdx.x;
    if (i < n4) b[i] = a[i];
}

__global__ void zero_out_kernel(float* __restrict__ p) {
    int i = blockIdx.x * blockDim.x + threadIdx.x;
    if (i < NGRAPH * DOUT) p[i] = 0.f;
}

// ---------------- fused readout second layers + gating + graph pooling ----------------
__global__ void readout_kernel(const float* __restrict__ i1, const float* __restrict__ j1,
                               const float* __restrict__ iw2, const float* __restrict__ ib2,
                               const float* __restrict__ jw2, const float* __restrict__ jb2,
                               const int* __restrict__ batch, float* __restrict__ out) {
    __shared__ float swi[HD * DOUT], swj[HD * DOUT], sbi[DOUT], sbj[DOUT];
    int tid = threadIdx.x;
    for (int k = tid; k < HD * DOUT; k += blockDim.x) { swi[k] = iw2[k]; swj[k] = jw2[k]; }
    if (tid < DOUT) { sbi[tid] = ib2[tid]; sbj[tid] = jb2[tid]; }
    __syncthreads();
    int n = blockIdx.x * blockDim.x + tid;
    if (n >= NNODES) return;
    float ia[DOUT], ja[DOUT];
#pragma unroll
    for (int c = 0; c < DOUT; c++) { ia[c] = sbi[c]; ja[c] = sbj[c]; }
    const float* ir = i1 + (size_t)n * HD;
    const float* jr = j1 + (size_t)n * HD;
    for (int k = 0; k < HD; k++) {
        float a = ir[k], b = jr[k];
#pragma unroll
        for (int c = 0; c < DOUT; c++) {
            ia[c] += a * swi[k * DOUT + c];
            ja[c] += b * swj[k * DOUT + c];
        }
    }
    int g = batch[n] * DOUT;
#pragma unroll
    for (int c = 0; c < DOUT; c++) {
        float iv = 1.f / (1.f + expf(-ia[c]));
        atomicAdd(&out[g + c], iv * ja[c]);
    }
}

// ---------------- host launcher ----------------
extern "C" void kernel_launch(void* const* d_in, const int* in_sizes, int n_in,
                              void* d_out, int out_size) {
    const float* x      = (const float*)d_in[0];
    const int*   ei     = (const int*)d_in[1];
    const int*   src    = ei;
    const int*   dst    = ei + NEDGES;
    const int*   eattr  = (const int*)d_in[2];
    const int*   batch  = (const int*)d_in[3];
    const float* lin0_w = (const float*)d_in[4];
    const float* lin0_b = (const float*)d_in[5];
    const float* eembed = (const float*)d_in[6];   // [5,64,64] == B[320,64] row-major
    const float* conv_b = (const float*)d_in[7];
    const float* w_ih   = (const float*)d_in[8];
    const float* w_hh   = (const float*)d_in[9];
    const float* b_ih   = (const float*)d_in[10];
    const float* b_hh   = (const float*)d_in[11];
    const float* i_w1   = (const float*)d_in[12];
    const float* i_b1   = (const float*)d_in[13];
    const float* i_w2   = (const float*)d_in[14];
    const float* i_b2   = (const float*)d_in[15];
    const float* j_w1   = (const float*)d_in[16];
    const float* j_b1   = (const float*)d_in[17];
    const float* j_w2   = (const float*)d_in[18];
    const float* j_b2   = (const float*)d_in[19];
    float* out = (float*)d_out;

    float *p_out0, *p_h, *p_m, *p_i1, *p_j1, *p_scr, *p_deginv;
    cudaGetSymbolAddress((void**)&p_out0, g_out0);
    cudaGetSymbolAddress((void**)&p_h, g_h);
    cudaGetSymbolAddress((void**)&p_m, g_m);
    cudaGetSymbolAddress((void**)&p_i1, g_i1);
    cudaGetSymbolAddress((void**)&p_j1, g_j1);
    cudaGetSymbolAddress((void**)&p_scr, g_scratch);
    cudaGetSymbolAddress((void**)&p_deginv, g_deginv);

    float* p_agg = p_scr;                              // [N,320]
    float* p_gx  = p_scr;                              // [N,192] (agg dead by then)
    float* p_gh  = p_scr + (size_t)NNODES * 192;       // [N,192]

    const int TB = 256;
    const int gN  = (NNODES + TB - 1) / TB;
    const int gE  = (NEDGES + TB - 1) / TB;
    const int gNH = (NNODES * HD + TB - 1) / TB;
    const int gW  = (NNODES * 32 + TB - 1) / TB;       // warp-per-node
    const int RB  = (NNODES + 127) / 128;              // GEMM row blocks

    // --- CSR build (deterministic work, repeated each call) ---
    zero_cnt_kernel<<<gN, TB>>>();
    hist_kernel<<<gE, TB>>>(dst);
    scan1_kernel<<<NB, SCAN_B>>>();
    scan2_kernel<<<1, 128>>>();
    scan3_kernel<<<gN, TB>>>();
    scatter_kernel<<<gE, TB>>>(src, dst, eattr);

    // --- lin0: out0 = relu(x @ lin0_w + b) ---
    gemm_kernel<1, false><<<dim3(RB, 1), TB>>>(x, nullptr, lin0_w, lin0_b, nullptr,
                                               p_out0, NNODES, DINP, HD);
    copy4_kernel<<<(NNODES * HD / 4 + TB - 1) / TB, TB>>>(
        (const float4*)p_out0, (float4*)p_h, NNODES * HD / 4);

    // --- propagation steps ---
    for (int step = 0; step < NSTEPS; step++) {
        agg_kernel<<<gW, TB>>>((const float2*)p_h, (float2*)p_agg);
        // m = relu(agg @ W_stack / deg + conv_bias)
        gemm_kernel<2, false><<<dim3(RB, 1), TB>>>(p_agg, nullptr, eembed, conv_b,
                                                   p_deginv, p_m, NNODES, NTYPE * HD, HD);
        // gx = m @ w_ih + b_ih ; gh = h @ w_hh + b_hh
        gemm_kernel<0, false><<<dim3(RB, 3), TB>>>(p_m, nullptr, w_ih, b_ih, nullptr,
                                                   p_gx, NNODES, HD, 3 * HD);
        gemm_kernel<0, false><<<dim3(RB, 3), TB>>>(p_h, nullptr, w_hh, b_hh, nullptr,
                                                   p_gh, NNODES, HD, 3 * HD);
        gru_kernel<<<gNH, TB>>>(p_gx, p_gh, p_h);
    }

    // --- readout ---
    gemm_kernel<3, true><<<dim3(RB, 1), TB>>>(p_h, p_out0, i_w1, i_b1, nullptr,
                                              p_i1, NNODES, 2 * HD, HD);
    gemm_kernel<3, false><<<dim3(RB, 1), TB>>>(p_h, nullptr, j_w1, j_b1, nullptr,
                                               p_j1, NNODES, HD, HD);
    zero_out_kernel<<<(NGRAPH * DOUT + TB - 1) / TB, TB>>>(out);
    readout_kernel<<<gN, TB>>>(p_i1, p_j1, i_w2, i_b2, j_w2, j_b2, batch, out);
}

// round 8
// speedup vs baseline: 1.2397x; 1.2397x over previous
#include <cuda_runtime.h>
#include <math.h>

#define NNODES 100000
#define NEDGES 3200000
#define HD 64
#define DINP 15
#define DOUT 12
#define NTYPE 5
#define NGRAPH 256
#define NSTEPS 6

#define SCAN_B 1024
#define NB ((NNODES + SCAN_B - 1) / SCAN_B)   // 98

// ---------------- scratch (device globals; no allocation) ----------------
__device__ float g_out0[NNODES * HD];
__device__ float g_h[NNODES * HD];
__device__ float g_m[NNODES * HD];
__device__ float g_i1[NNODES * HD];
__device__ float g_j1[NNODES * HD];
__device__ float g_scratch[(size_t)NNODES * 384];   // agg[N,320] / gx[N,192] / gh[N,192]
__device__ float g_deginv[NNODES];
__device__ int   g_rowptr[NNODES + 1];
__device__ int   g_cnt[NNODES];
__device__ int   g_cursor[NNODES];
__device__ int   g_bsums[128];
__device__ int   g_ecsr[NEDGES];

// ---------------- CSR build ----------------
__global__ void zero_cnt_kernel() {
    int i = blockIdx.x * blockDim.x + threadIdx.x;
    if (i < NNODES) g_cnt[i] = 0;
}

__global__ void hist_kernel(const int* __restrict__ dst) {
    int e = blockIdx.x * blockDim.x + threadIdx.x;
    if (e < NEDGES) atomicAdd(&g_cnt[dst[e]], 1);
}

__global__ void scan1_kernel() {
    __shared__ int s[SCAN_B];
    int tid = threadIdx.x;
    int g = blockIdx.x * SCAN_B + tid;
    int v = (g < NNODES) ? g_cnt[g] : 0;
    s[tid] = v;
    __syncthreads();
    for (int off = 1; off < SCAN_B; off <<= 1) {
        int t = (tid >= off) ? s[tid - off] : 0;
        __syncthreads();
        s[tid] += t;
        __syncthreads();
    }
    if (g < NNODES) g_rowptr[g] = s[tid] - v;          // block-local exclusive
    if (tid == SCAN_B - 1) g_bsums[blockIdx.x] = s[tid];
}

__global__ void scan2_kernel() {
    __shared__ int s[128];
    int tid = threadIdx.x;
    int v = (tid < NB) ? g_bsums[tid] : 0;
    s[tid] = v;
    __syncthreads();
    for (int off = 1; off < 128; off <<= 1) {
        int t = (tid >= off) ? s[tid - off] : 0;
        __syncthreads();
        s[tid] += t;
        __syncthreads();
    }
    if (tid < NB) g_bsums[tid] = s[tid] - v;           // exclusive block offsets
    if (tid == 127) g_rowptr[NNODES] = s[127];         // = E
}

__global__ void scan3_kernel() {
    int g = blockIdx.x * blockDim.x + threadIdx.x;
    if (g >= NNODES) return;
    g_rowptr[g] += g_bsums[g >> 10];
    g_cursor[g] = 0;
    int d = g_cnt[g];
    g_deginv[g] = 1.0f / (float)(d > 0 ? d : 1);
}

__global__ void scatter_kernel(const int* __restrict__ src,
                               const int* __restrict__ dst,
                               const int* __restrict__ typ) {
    int e = blockIdx.x * blockDim.x + threadIdx.x;
    if (e >= NEDGES) return;
    int d = dst[e];
    int pos = atomicAdd(&g_cursor[d], 1);
    g_ecsr[g_rowptr[d] + pos] = src[e] | (typ[e] << 17);  // N < 2^17, type < 8
}

// ================= tf32 tensor-core GEMM =================
// C[nrows,M] = A[nrows,K] @ B[K,M] + epilogue.  K % 32 == 0, M % 64 == 0.
// EPI: 0 = +bias; 2 = relu(acc*rowscale + bias); 3 = sigmoid(+bias)
// Tile: 128x64 per block, 8 warps (4 row x 2 col), warp tile 32x32,
// mma.sync.m16n8k8.tf32 (2x4 mma tiles per warp, 32 fp32 acc regs/thread).

__device__ __forceinline__ void mma_tf32(float* d, const unsigned* a, const unsigned* b) {
    asm volatile(
        "mma.sync.aligned.m16n8k8.row.col.f32.tf32.tf32.f32 "
        "{%0,%1,%2,%3}, {%4,%5,%6,%7}, {%8,%9}, {%0,%1,%2,%3};\n"
        : "+f"(d[0]), "+f"(d[1]), "+f"(d[2]), "+f"(d[3])
        : "r"(a[0]), "r"(a[1]), "r"(a[2]), "r"(a[3]), "r"(b[0]), "r"(b[1]));
}

template <int EPI, bool CONCAT>
__global__ void __launch_bounds__(256)
mma_gemm_kernel(const float* __restrict__ A, const float* __restrict__ A2,
                const float* __restrict__ B, const float* __restrict__ bias,
                const float* __restrict__ rowscale, float* __restrict__ C,
                int nrows, int K, int M) {
    __shared__ float As[128 * 36];   // [row][k] stride 36: bank=(4r+c)%32, conflict-free frags
    __shared__ float Bs[32 * 72];    // [k][n]  stride 72: bank=(8k+n)%32, conflict-free frags
    const int tid = threadIdx.x;
    const int lane = tid & 31;
    const int wid = tid >> 5;
    const int warpRow = wid >> 1;     // 0..3 -> rows warpRow*32
    const int warpCol = wid & 1;      // 0..1 -> cols warpCol*32
    const int g = lane >> 2;          // groupID 0..7
    const int tig = lane & 3;         // thread-in-group 0..3
    const int rowBlk = blockIdx.x * 128;
    const int colBlk = blockIdx.y * 64;

    float acc[2][4][4];
#pragma unroll
    for (int mt = 0; mt < 2; mt++)
#pragma unroll
        for (int nt = 0; nt < 4; nt++)
#pragma unroll
            for (int i = 0; i < 4; i++) acc[mt][nt][i] = 0.f;

    const int arow = tid >> 1;            // 0..127
    const int aseg = (tid & 1) * 16;      // 0 or 16
    const int brow = tid >> 4;            // 0..15
    const int bcol4 = (tid & 15) * 4;     // 0..60

    for (int k0 = 0; k0 < K; k0 += 32) {
        // --- A tile 128x32 ---
        if (rowBlk + arow < nrows) {
#pragma unroll
            for (int i = 0; i < 4; i++) {
                int kk = k0 + aseg + i * 4;
                float4 v;
                if (CONCAT) {
                    const float* srcp = (kk < HD)
                        ? (A  + (size_t)(rowBlk + arow) * HD + kk)
                        : (A2 + (size_t)(rowBlk + arow) * HD + (kk - HD));
                    v = *reinterpret_cast<const float4*>(srcp);
                } else {
                    v = *reinterpret_cast<const float4*>(A + (size_t)(rowBlk + arow) * K + kk);
                }
                *reinterpret_cast<float4*>(&As[arow * 36 + aseg + i * 4]) = v;
            }
        } else {
            float4 z = make_float4(0.f, 0.f, 0.f, 0.f);
#pragma unroll
            for (int i = 0; i < 4; i++)
                *reinterpret_cast<float4*>(&As[arow * 36 + aseg + i * 4]) = z;
        }
        // --- B tile 32x64 (M multiple of 64, K multiple of 32: no guards) ---
#pragma unroll
        for (int i = 0; i < 2; i++) {
            int bk = brow + i * 16;
            float4 v = *reinterpret_cast<const float4*>(
                B + (size_t)(k0 + bk) * M + colBlk + bcol4);
            *reinterpret_cast<float4*>(&Bs[bk * 72 + bcol4]) = v;
        }
        __syncthreads();

#pragma unroll
        for (int kk = 0; kk < 32; kk += 8) {
            unsigned a[2][4], b[4][2];
#pragma unroll
            for (int mt = 0; mt < 2; mt++) {
                int rb = warpRow * 32 + mt * 16;
                a[mt][0] = __float_as_uint(As[(rb + g)     * 36 + kk + tig]);
                a[mt][1] = __float_as_uint(As[(rb + g + 8) * 36 + kk + tig]);
                a[mt][2] = __float_as_uint(As[(rb + g)     * 36 + kk + tig + 4]);
                a[mt][3] = __float_as_uint(As[(rb + g + 8) * 36 + kk + tig + 4]);
            }
#pragma unroll
            for (int nt = 0; nt < 4; nt++) {
                int nb = warpCol * 32 + nt * 8 + g;
                b[nt][0] = __float_as_uint(Bs[(kk + tig)     * 72 + nb]);
                b[nt][1] = __float_as_uint(Bs[(kk + tig + 4) * 72 + nb]);
            }
#pragma unroll
            for (int mt = 0; mt < 2; mt++)
#pragma unroll
                for (int nt = 0; nt < 4; nt++)
                    mma_tf32(acc[mt][nt], a[mt], b[nt]);
        }
        __syncthreads();
    }

    // --- epilogue: c0/c1 -> (row=g, cols 2tig,2tig+1), c2/c3 -> row=g+8 ---
#pragma unroll
    for (int mt = 0; mt < 2; mt++) {
        int r0 = rowBlk + warpRow * 32 + mt * 16 + g;
        int r1 = r0 + 8;
        float rs0 = 1.f, rs1 = 1.f;
        if (EPI == 2) {
            if (r0 < nrows) rs0 = rowscale[r0];
            if (r1 < nrows) rs1 = rowscale[r1];
        }
#pragma unroll
        for (int nt = 0; nt < 4; nt++) {
            int c = colBlk + warpCol * 32 + nt * 8 + 2 * tig;
            float bv0 = bias[c], bv1 = bias[c + 1];
            if (r0 < nrows) {
                float v0 = acc[mt][nt][0], v1 = acc[mt][nt][1];
                if (EPI == 2) { v0 *= rs0; v1 *= rs0; }
                v0 += bv0; v1 += bv1;
                if (EPI == 2) { v0 = fmaxf(v0, 0.f); v1 = fmaxf(v1, 0.f); }
                if (EPI == 3) { v0 = 1.f / (1.f + expf(-v0)); v1 = 1.f / (1.f + expf(-v1)); }
                *reinterpret_cast<float2*>(C + (size_t)r0 * M + c) = make_float2(v0, v1);
            }
            if (r1 < nrows) {
                float v0 = acc[mt][nt][2], v1 = acc[mt][nt][3];
                if (EPI == 2) { v0 *= rs1; v1 *= rs1; }
                v0 += bv0; v1 += bv1;
                if (EPI == 2) { v0 = fmaxf(v0, 0.f); v1 = fmaxf(v1, 0.f); }
                if (EPI == 3) { v0 = 1.f / (1.f + expf(-v0)); v1 = 1.f / (1.f + expf(-v1)); }
                *reinterpret_cast<float2*>(C + (size_t)r1 * M + c) = make_float2(v0, v1);
            }
        }
    }
}

// ---------------- fp32 FFMA GEMM (kept for lin0, K=15; writes C and optional C2) ----
__global__ void __launch_bounds__(256)
gemm_lin0_kernel(const float* __restrict__ A, const float* __restrict__ B,
                 const float* __restrict__ bias, float* __restrict__ C,
                 float* __restrict__ C2, int nrows, int K, int M) {
    __shared__ float As[128 * 17];
    __shared__ float Bs[16 * 64];
    const int tid = threadIdx.x;
    const int tx = tid & 15;
    const int ty = tid >> 4;
    const int rowBlk = blockIdx.x * 128;

    float acc[8][4];
#pragma unroll
    for (int i = 0; i < 8; i++)
#pragma unroll
        for (int j = 0; j < 4; j++) acc[i][j] = 0.f;

    const int m_ld = tid >> 1;
    const int kh = (tid & 1) * 8;
    const int grow = rowBlk + m_ld;

    for (int k0 = 0; k0 < K; k0 += 16) {
#pragma unroll
        for (int j = 0; j < 8; j++) {
            int kk = k0 + kh + j;
            float v = 0.f;
            if (grow < nrows && kk < K) v = A[(size_t)grow * K + kk];
            As[m_ld * 17 + kh + j] = v;
        }
        {
            int idx = tid * 4;
            int bk = idx >> 6;
            int bn = idx & 63;
#pragma unroll
            for (int j = 0; j < 4; j++) {
                int gk = k0 + bk;
                Bs[bk * 64 + bn + j] = (gk < K) ? __ldg(&B[gk * M + bn + j]) : 0.f;
            }
        }
        __syncthreads();
#pragma unroll
        for (int kk = 0; kk < 16; kk++) {
            float4 b4 = *reinterpret_cast<const float4*>(&Bs[kk * 64 + tx * 4]);
            float a[8];
#pragma unroll
            for (int i = 0; i < 8; i++) a[i] = As[(ty * 8 + i) * 17 + kk];
#pragma unroll
            for (int i = 0; i < 8; i++) {
                acc[i][0] += a[i] * b4.x;
                acc[i][1] += a[i] * b4.y;
                acc[i][2] += a[i] * b4.z;
                acc[i][3] += a[i] * b4.w;
            }
        }
        __syncthreads();
    }
#pragma unroll
    for (int i = 0; i < 8; i++) {
        int r = rowBlk + ty * 8 + i;
        if (r >= nrows) break;
#pragma unroll
        for (int j = 0; j < 4; j++) {
            int c = tx * 4 + j;
            float v = fmaxf(acc[i][j] + bias[c], 0.f);
            C[(size_t)r * M + c] = v;
            C2[(size_t)r * M + c] = v;
        }
    }
}

// ---------------- per-type neighbor aggregation (warp per node) ----------------
__global__ void agg_kernel(const float2* __restrict__ out2, float2* __restrict__ agg2) {
    int w = (blockIdx.x * blockDim.x + threadIdx.x) >> 5;
    int lane = threadIdx.x & 31;
    if (w >= NNODES) return;
    int s = g_rowptr[w];
    int e = g_rowptr[w + 1];
    float2 acc[NTYPE];
#pragma unroll
    for (int t = 0; t < NTYPE; t++) { acc[t].x = 0.f; acc[t].y = 0.f; }
    int i = s;
    for (; i + 1 < e; i += 2) {
        int e0 = __ldg(&g_ecsr[i]);
        int e1 = __ldg(&g_ecsr[i + 1]);
        float2 v0 = out2[(e0 & 0x1FFFF) * 32 + lane];
        float2 v1 = out2[(e1 & 0x1FFFF) * 32 + lane];
        int t0 = e0 >> 17, t1 = e1 >> 17;
#pragma unroll
        for (int t = 0; t < NTYPE; t++) {
            if (t0 == t) { acc[t].x += v0.x; acc[t].y += v0.y; }
            if (t1 == t) { acc[t].x += v1.x; acc[t].y += v1.y; }
        }
    }
    if (i < e) {
        int e0 = __ldg(&g_ecsr[i]);
        float2 v0 = out2[(e0 & 0x1FFFF) * 32 + lane];
        int t0 = e0 >> 17;
#pragma unroll
        for (int t = 0; t < NTYPE; t++)
            if (t0 == t) { acc[t].x += v0.x; acc[t].y += v0.y; }
    }
    size_t base = (size_t)w * (NTYPE * 32);
#pragma unroll
    for (int t = 0; t < NTYPE; t++) agg2[base + t * 32 + lane] = acc[t];
}

// ---------------- GRU elementwise ----------------
__global__ void gru_kernel(const float* __restrict__ gx, const float* __restrict__ gh,
                           float* __restrict__ h) {
    int idx = blockIdx.x * blockDim.x + threadIdx.x;
    if (idx >= NNODES * HD) return;
    int n = idx >> 6, c = idx & 63;
    size_t b = (size_t)n * 192 + c;
    float xr = gx[b], xz = gx[b + 64], xn = gx[b + 128];
    float hr = gh[b], hz = gh[b + 64], hn = gh[b + 128];
    float r = 1.f / (1.f + expf(-(xr + hr)));
    float z = 1.f / (1.f + expf(-(xz + hz)));
    float nn = tanhf(xn + r * hn);
    float hv = h[idx];
    h[idx] = (1.f - z) * nn + z * hv;
}

__global__ void zero_out_kernel(float* __restrict__ p) {
    int i = blockIdx.x * blockDim.x + threadIdx.x;
    if (i < NGRAPH * DOUT) p[i] = 0.f;
}

// ---------------- fused readout second layers + gating + graph pooling ----------------
__global__ void readout_kernel(const float* __restrict__ i1, const float* __restrict__ j1,
                               const float* __restrict__ iw2, const float* __restrict__ ib2,
                               const float* __restrict__ jw2, const float* __restrict__ jb2,
                               const int* __restrict__ batch, float* __restrict__ out) {
    __shared__ float swi[HD * DOUT], swj[HD * DOUT], sbi[DOUT], sbj[DOUT];
    int tid = threadIdx.x;
    for (int k = tid; k < HD * DOUT; k += blockDim.x) { swi[k] = iw2[k]; swj[k] = jw2[k]; }
    if (tid < DOUT) { sbi[tid] = ib2[tid]; sbj[tid] = jb2[tid]; }
    __syncthreads();
    int n = blockIdx.x * blockDim.x + tid;
    if (n >= NNODES) return;
    float ia[DOUT], ja[DOUT];
#pragma unroll
    for (int c = 0; c < DOUT; c++) { ia[c] = sbi[c]; ja[c] = sbj[c]; }
    const float* ir = i1 + (size_t)n * HD;
    const float* jr = j1 + (size_t)n * HD;
    for (int k = 0; k < HD; k++) {
        float a = ir[k], b = jr[k];
#pragma unroll
        for (int c = 0; c < DOUT; c++) {
            ia[c] += a * swi[k * DOUT + c];
            ja[c] += b * swj[k * DOUT + c];
        }
    }
    int g = batch[n] * DOUT;
#pragma unroll
    for (int c = 0; c < DOUT; c++) {
        float iv = 1.f / (1.f + expf(-ia[c]));
        atomicAdd(&out[g + c], iv * ja[c]);
    }
}

// ---------------- host launcher ----------------
extern "C" void kernel_launch(void* const* d_in, const int* in_sizes, int n_in,
                              void* d_out, int out_size) {
    const float* x      = (const float*)d_in[0];
    const int*   ei     = (const int*)d_in[1];
    const int*   src    = ei;
    const int*   dst    = ei + NEDGES;
    const int*   eattr  = (const int*)d_in[2];
    const int*   batch  = (const int*)d_in[3];
    const float* lin0_w = (const float*)d_in[4];
    const float* lin0_b = (const float*)d_in[5];
    const float* eembed = (const float*)d_in[6];   // [5,64,64] == B[320,64] row-major
    const float* conv_b = (const float*)d_in[7];
    const float* w_ih   = (const float*)d_in[8];
    const float* w_hh   = (const float*)d_in[9];
    const float* b_ih   = (const float*)d_in[10];
    const float* b_hh   = (const float*)d_in[11];
    const float* i_w1   = (const float*)d_in[12];
    const float* i_b1   = (const float*)d_in[13];
    const float* i_w2   = (const float*)d_in[14];
    const float* i_b2   = (const float*)d_in[15];
    const float* j_w1   = (const float*)d_in[16];
    const float* j_b1   = (const float*)d_in[17];
    const float* j_w2   = (const float*)d_in[18];
    const float* j_b2   = (const float*)d_in[19];
    float* out = (float*)d_out;

    float *p_out0, *p_h, *p_m, *p_i1, *p_j1, *p_scr, *p_deginv;
    cudaGetSymbolAddress((void**)&p_out0, g_out0);
    cudaGetSymbolAddress((void**)&p_h, g_h);
    cudaGetSymbolAddress((void**)&p_m, g_m);
    cudaGetSymbolAddress((void**)&p_i1, g_i1);
    cudaGetSymbolAddress((void**)&p_j1, g_j1);
    cudaGetSymbolAddress((void**)&p_scr, g_scratch);
    cudaGetSymbolAddress((void**)&p_deginv, g_deginv);

    float* p_agg = p_scr;                              // [N,320]
    float* p_gx  = p_scr;                              // [N,192] (agg dead by then)
    float* p_gh  = p_scr + (size_t)NNODES * 192;       // [N,192]

    const int TB = 256;
    const int gN  = (NNODES + TB - 1) / TB;
    const int gE  = (NEDGES + TB - 1) / TB;
    const int gNH = (NNODES * HD + TB - 1) / TB;
    const int gW  = (NNODES * 32 + TB - 1) / TB;       // warp-per-node
    const int RB  = (NNODES + 127) / 128;              // GEMM row blocks

    // --- CSR build (deterministic work, repeated each call) ---
    zero_cnt_kernel<<<gN, TB>>>();
    hist_kernel<<<gE, TB>>>(dst);
    scan1_kernel<<<NB, SCAN_B>>>();
    scan2_kernel<<<1, 128>>>();
    scan3_kernel<<<gN, TB>>>();
    scatter_kernel<<<gE, TB>>>(src, dst, eattr);

    // --- lin0: out0 = h = relu(x @ lin0_w + b) (fused double-write) ---
    gemm_lin0_kernel<<<RB, TB>>>(x, lin0_w, lin0_b, p_out0, p_h, NNODES, DINP, HD);

    // --- propagation steps (tensor-core tf32 GEMMs) ---
    for (int step = 0; step < NSTEPS; step++) {
        agg_kernel<<<gW, TB>>>((const float2*)p_h, (float2*)p_agg);
        // m = relu(agg @ W_stack * deginv + conv_bias)
        mma_gemm_kernel<2, false><<<dim3(RB, 1), TB>>>(p_agg, nullptr, eembed, conv_b,
                                                       p_deginv, p_m, NNODES, NTYPE * HD, HD);
        // gx = m @ w_ih + b_ih ; gh = h @ w_hh + b_hh
        mma_gemm_kernel<0, false><<<dim3(RB, 3), TB>>>(p_m, nullptr, w_ih, b_ih, nullptr,
                                                       p_gx, NNODES, HD, 3 * HD);
        mma_gemm_kernel<0, false><<<dim3(RB, 3), TB>>>(p_h, nullptr, w_hh, b_hh, nullptr,
                                                       p_gh, NNODES, HD, 3 * HD);
        gru_kernel<<<gNH, TB>>>(p_gx, p_gh, p_h);
    }

    // --- readout ---
    mma_gemm_kernel<3, true><<<dim3(RB, 1), TB>>>(p_h, p_out0, i_w1, i_b1, nullptr,
                                                  p_i1, NNODES, 2 * HD, HD);
    mma_gemm_kernel<3, false><<<dim3(RB, 1), TB>>>(p_h, nullptr, j_w1, j_b1, nullptr,
                                                   p_j1, NNODES, HD, HD);
    zero_out_kernel<<<(NGRAPH * DOUT + TB - 1) / TB, TB>>>(out);
    readout_kernel<<<gN, TB>>>(p_i1, p_j1, i_w2, i_b2, j_w2, j_b2, batch, out);
}